// round 10
// baseline (speedup 1.0000x reference)
#include <cuda_runtime.h>
#include <cuda_fp16.h>
#include <cstdint>

// out = x @ (Wv@Wo) + (bv@Wo + bo)   (algebraic collapse, validated r1)
// Single fused launch: producer CTAs (combine Wc + bias) + consumer CTAs (fp16
// mma GEMM) synchronized by a release/acquire counter. rel_err 2.94e-4 measured.

#define D 512

__device__ __half g_Bhi[D * D];   // WcT fp16  [n][k]
__device__ float g_bc[D];
__device__ int g_done = 0;        // producer completion counter (self-resetting)
__device__ int g_fin  = 0;        // consumer completion counter

#define N_COMBINE 64
#define N_BC 8
#define N_PROD (N_COMBINE + N_BC)     // 72
#define N_TILES 512                   // 4 n-blocks x 128 m-blocks

// ───────────────────────── helpers ─────────────────────────
__device__ __forceinline__ uint32_t smem_u32(const void* p) {
    uint32_t a;
    asm("{ .reg .u64 t; cvta.to.shared.u64 t, %1; cvt.u32.u64 %0, t; }"
        : "=r"(a) : "l"(p));
    return a;
}
__device__ __forceinline__ void cp16(uint32_t dst, const void* src) {
    asm volatile("cp.async.cg.shared.global [%0], [%1], 16;"
                 :: "r"(dst), "l"(src) : "memory");
}
__device__ __forceinline__ void cp_commit() {
    asm volatile("cp.async.commit_group;" ::: "memory");
}
template <int N>
__device__ __forceinline__ void cp_wait() {
    asm volatile("cp.async.wait_group %0;" :: "n"(N) : "memory");
}
__device__ __forceinline__ void ldsm_x4(uint32_t (&r)[4], uint32_t addr) {
    asm volatile("ldmatrix.sync.aligned.m8n8.x4.shared.b16 {%0,%1,%2,%3}, [%4];"
                 : "=r"(r[0]), "=r"(r[1]), "=r"(r[2]), "=r"(r[3]) : "r"(addr));
}
__device__ __forceinline__ void mma_f16(float (&d)[4], const uint32_t (&a)[4],
                                        uint32_t b0, uint32_t b1) {
    asm volatile(
        "mma.sync.aligned.m16n8k16.row.col.f32.f16.f16.f32 "
        "{%0,%1,%2,%3}, {%4,%5,%6,%7}, {%8,%9}, {%0,%1,%2,%3};"
        : "+f"(d[0]), "+f"(d[1]), "+f"(d[2]), "+f"(d[3])
        : "r"(a[0]), "r"(a[1]), "r"(a[2]), "r"(a[3]), "r"(b0), "r"(b1));
}

// ───────────── GEMM geometry ─────────────
#define BM 128
#define BN 128
#define BKK 32
#define ROWB 80
#define A_TILE (128 * ROWB)
#define B_TILE (128 * ROWB)
#define A_STAGES 2
#define B_STAGES 4
#define B_BASE (A_STAGES * A_TILE)
#define SMEM_TOTAL (A_STAGES * A_TILE + B_STAGES * B_TILE)   // 61440 B
#define NKB (D / BKK)   // 16

__global__ __launch_bounds__(256, 2)
void fused_kernel(const float* __restrict__ x,
                  const float* __restrict__ Wv, const float* __restrict__ Wo,
                  const float* __restrict__ bv, const float* __restrict__ bo,
                  const __half* __restrict__ Bhi,
                  const float* __restrict__ bc, float* __restrict__ out)
{
    extern __shared__ char smem[];
    const int bid = blockIdx.x;
    const int tid = threadIdx.x;

    // ═════════ producers ═════════
    if (bid < N_PROD) {
        if (bid < N_COMBINE) {
            // ---- combine: 64x64 tile of Wc = Wv@Wo, 4x4 microtile ----
            float (*As)[68] = reinterpret_cast<float(*)[68]>(smem);
            float (*Bs)[68] = reinterpret_cast<float(*)[68]>(smem + 32 * 68 * 4);
            const int kb0 = (bid >> 3) * 64;
            const int nb0 = (bid & 7) * 64;
            const int ty = (tid >> 4) * 4;
            const int tx = (tid & 15) * 4;

            float acc[4][4] = {};
            for (int k0 = 0; k0 < D; k0 += 32) {
                #pragma unroll
                for (int u = 0; u < 2; u++) {
                    const int idx = tid + u * 256;
                    const int r = idx >> 3, c = (idx & 7) * 4;
                    float4 va = *reinterpret_cast<const float4*>(
                        &Wv[(size_t)(kb0 + r) * D + k0 + c]);
                    As[c + 0][r] = va.x; As[c + 1][r] = va.y;
                    As[c + 2][r] = va.z; As[c + 3][r] = va.w;
                }
                #pragma unroll
                for (int u = 0; u < 2; u++) {
                    const int idx = tid + u * 256;
                    const int r = idx >> 4, c = (idx & 15) * 4;
                    *reinterpret_cast<float4*>(&Bs[r][c]) =
                        *reinterpret_cast<const float4*>(
                            &Wo[(size_t)(k0 + r) * D + nb0 + c]);
                }
                __syncthreads();
                #pragma unroll
                for (int k = 0; k < 32; k++) {
                    float4 ra = *reinterpret_cast<const float4*>(&As[k][ty]);
                    float4 rb = *reinterpret_cast<const float4*>(&Bs[k][tx]);
                    const float a4[4] = {ra.x, ra.y, ra.z, ra.w};
                    const float b4[4] = {rb.x, rb.y, rb.z, rb.w};
                    #pragma unroll
                    for (int i = 0; i < 4; i++)
                        #pragma unroll
                        for (int j = 0; j < 4; j++)
                            acc[i][j] += a4[i] * b4[j];
                }
                __syncthreads();
            }
            #pragma unroll
            for (int i = 0; i < 4; i++)
                #pragma unroll
                for (int j = 0; j < 4; j++) {
                    const int k = kb0 + ty + i;
                    const int n = nb0 + tx + j;
                    g_Bhi[(size_t)n * D + k] = __float2half_rn(acc[i][j]);
                }
        } else {
            // ---- bc: 8 blocks x 64 n-cols, coalesced row reads ----
            float (*red)[64] = reinterpret_cast<float(*)[64]>(smem);
            const int n0 = (bid - N_COMBINE) * 64;
            const int nn = tid & 63;
            const int kk = tid >> 6;
            float s = 0.f;
            #pragma unroll 16
            for (int k = kk; k < D; k += 4)
                s += bv[k] * Wo[(size_t)k * D + n0 + nn];
            red[kk][nn] = s;
            __syncthreads();
            if (tid < 64)
                g_bc[n0 + tid] = red[0][tid] + red[1][tid] + red[2][tid]
                               + red[3][tid] + bo[n0 + tid];
        }
        // release: data visible before counter increment
        __threadfence();
        __syncthreads();
        if (tid == 0) atomicAdd(&g_done, 1);
        return;
    }

    // ═════════ consumers: fp16 mma GEMM ═════════
    const uint32_t sb = smem_u32(smem);
    const int lane = tid & 31;
    const int wid = tid >> 5;
    const int c = bid - N_PROD;
    const int n0 = (c & 3) * BN;      // n fast: 4 CTAs share an A tile
    const int m0 = (c >> 2) * BM;
    const int wm = (wid >> 2) * 64;
    const int wn = (wid & 3) * 32;

    const int ar = tid >> 3;
    const int ac = tid & 7;

    float4 areg[4];

    auto lda = [&](int kb) {
        const int k0 = kb * BKK;
        #pragma unroll
        for (int u = 0; u < 4; u++) {
            const int r = ar + u * 32;
            areg[u] = __ldg(reinterpret_cast<const float4*>(
                &x[(size_t)(m0 + r) * D + k0 + ac * 4]));
        }
    };
    auto sta = [&](int s) {
        char* base = smem + s * A_TILE;
        #pragma unroll
        for (int u = 0; u < 4; u++) {
            const int r = ar + u * 32;
            __half2 h0 = __floats2half2_rn(areg[u].x, areg[u].y);
            __half2 h1 = __floats2half2_rn(areg[u].z, areg[u].w);
            uint2 v;
            v.x = *reinterpret_cast<uint32_t*>(&h0);
            v.y = *reinterpret_cast<uint32_t*>(&h1);
            *reinterpret_cast<uint2*>(base + r * ROWB + ac * 8) = v;
        }
    };
    auto ldb = [&](int kb, int s) {
        const uint32_t base = sb + B_BASE + (uint32_t)s * B_TILE;
        const int k0 = kb * BKK;
        #pragma unroll
        for (int u = 0; u < 2; u++) {
            const int ch = tid + u * 256;
            const int r = ch >> 2, cc = ch & 3;
            cp16(base + r * ROWB + cc * 16,
                 Bhi + (size_t)(n0 + r) * D + k0 + cc * 8);
        }
    };

    float acc[4][4][4] = {};

    // A prologue first (independent of producers)
    lda(0); sta(0);
    lda(1);

    // acquire-wait for all producers
    if (tid == 0) {
        int v;
        do {
            asm volatile("ld.acquire.gpu.global.b32 %0, [%1];"
                         : "=r"(v) : "l"(&g_done) : "memory");
            if (v < N_PROD) __nanosleep(128);
        } while (v < N_PROD);
    }
    __syncthreads();

    // B prologue: stages 0..2 (prefetch distance 3)
    ldb(0, 0); cp_commit();
    ldb(1, 1); cp_commit();
    ldb(2, 2); cp_commit();

    #pragma unroll
    for (int kb = 0; kb < NKB; kb++) {
        if (kb <= NKB - 3)      cp_wait<2>();
        else if (kb == NKB - 2) cp_wait<1>();
        else                    cp_wait<0>();
        __syncthreads();

        // dependency-safe front-loading: sta(kb+1) consumes areg, then refill
        if (kb + 1 < NKB) sta((kb + 1) & 1);
        if (kb + 2 < NKB) lda(kb + 2);
        if (kb + 3 < NKB) ldb(kb + 3, (kb + 3) & 3);
        cp_commit();

        const uint32_t baseA = sb + (uint32_t)(kb & 1) * A_TILE;
        const uint32_t baseB = sb + B_BASE + (uint32_t)(kb & 3) * B_TILE;
        #pragma unroll
        for (int ks = 0; ks < 2; ks++) {
            uint32_t a[4][4];
            #pragma unroll
            for (int mi = 0; mi < 4; mi++) {
                uint32_t ra = baseA + (uint32_t)(wm + mi * 16 + (lane & 15)) * ROWB
                            + ks * 32 + ((lane >> 4) << 4);
                ldsm_x4(a[mi], ra);
            }
            uint32_t bh[2][4];
            #pragma unroll
            for (int bi = 0; bi < 2; bi++) {
                const int nl = wn + bi * 16 + (lane & 7) + ((lane >> 4) << 3);
                uint32_t rb = baseB + (uint32_t)nl * ROWB
                            + ks * 32 + (((lane >> 3) & 1) << 4);
                ldsm_x4(bh[bi], rb);
            }
            #pragma unroll
            for (int mi = 0; mi < 4; mi++)
                #pragma unroll
                for (int ni = 0; ni < 4; ni++) {
                    const int bi = ni >> 1, p = (ni & 1) * 2;
                    mma_f16(acc[mi][ni], a[mi], bh[bi][p], bh[bi][p + 1]);
                }
        }
    }

    // epilogue: fp32 stores + bias
    #pragma unroll
    for (int mi = 0; mi < 4; mi++) {
        const int r = m0 + wm + mi * 16 + (lane >> 2);
        #pragma unroll
        for (int ni = 0; ni < 4; ni++) {
            const int cc = n0 + wn + ni * 8 + (lane & 3) * 2;
            float2 bvv = *reinterpret_cast<const float2*>(&bc[cc]);
            float2 v0 = make_float2(acc[mi][ni][0] + bvv.x, acc[mi][ni][1] + bvv.y);
            float2 v1 = make_float2(acc[mi][ni][2] + bvv.x, acc[mi][ni][3] + bvv.y);
            *reinterpret_cast<float2*>(&out[(size_t)r * D + cc]) = v0;
            *reinterpret_cast<float2*>(&out[(size_t)(r + 8) * D + cc]) = v1;
        }
    }

    // deterministic self-reset: the last finishing consumer zeroes the counters
    // (all consumers have passed the acquire-wait by construction).
    __syncthreads();
    if (tid == 0) {
        const int f = atomicAdd(&g_fin, 1);
        if (f == N_TILES - 1) {
            g_done = 0;
            g_fin = 0;
            __threadfence();
        }
    }
}

// ───────────────────────── host ─────────────────────────
extern "C" void kernel_launch(void* const* d_in, const int* in_sizes, int n_in,
                              void* d_out, int out_size)
{
    // order: x, H, W, Wq, bq, Wk, bk, Wv, bv, Wo, bo, Woff1, boff1, Woff2, boff2
    const float* x  = (const float*)d_in[0];
    const float* Wv = (const float*)d_in[7];
    const float* bv = (const float*)d_in[8];
    const float* Wo = (const float*)d_in[9];
    const float* bo = (const float*)d_in[10];
    float* out = (float*)d_out;

    __half* bhi;
    float* bc;
    cudaGetSymbolAddress((void**)&bhi, g_Bhi);
    cudaGetSymbolAddress((void**)&bc,  g_bc);

    static bool attr_set = false;
    if (!attr_set) {
        cudaFuncSetAttribute(fused_kernel,
                             cudaFuncAttributeMaxDynamicSharedMemorySize, SMEM_TOTAL);
        attr_set = true;
    }

    fused_kernel<<<N_PROD + N_TILES, 256, SMEM_TOTAL>>>(
        x, Wv, Wo, bv, bo, bhi, bc, out);
}

// round 11
// speedup vs baseline: 1.2199x; 1.2199x over previous
#include <cuda_runtime.h>
#include <cuda_fp16.h>
#include <cstdint>

// out = x @ (Wv@Wo) + (bv@Wo + bo)   (algebraic collapse, validated r1)
// Main GEMM: single-pass fp16 mma.sync, inline fp32->fp16 A conversion.
// Combine GEMM (Wc=Wv@Wo) now ALSO on tensor cores (fp16 in / fp32 accum),
// with convert-transpose smem stores for the Wo operand.

#define D 512

__device__ __half g_Bhi[D * D];   // WcT fp16  [n][k]
__device__ float g_bc[D];

// ───────────────────────── helpers ─────────────────────────
__device__ __forceinline__ uint32_t smem_u32(const void* p) {
    uint32_t a;
    asm("{ .reg .u64 t; cvta.to.shared.u64 t, %1; cvt.u32.u64 %0, t; }"
        : "=r"(a) : "l"(p));
    return a;
}
__device__ __forceinline__ void cp16(uint32_t dst, const void* src) {
    asm volatile("cp.async.cg.shared.global [%0], [%1], 16;"
                 :: "r"(dst), "l"(src) : "memory");
}
__device__ __forceinline__ void cp_commit() {
    asm volatile("cp.async.commit_group;" ::: "memory");
}
template <int N>
__device__ __forceinline__ void cp_wait() {
    asm volatile("cp.async.wait_group %0;" :: "n"(N) : "memory");
}
__device__ __forceinline__ void ldsm_x4(uint32_t (&r)[4], uint32_t addr) {
    asm volatile("ldmatrix.sync.aligned.m8n8.x4.shared.b16 {%0,%1,%2,%3}, [%4];"
                 : "=r"(r[0]), "=r"(r[1]), "=r"(r[2]), "=r"(r[3]) : "r"(addr));
}
__device__ __forceinline__ void mma_f16(float (&d)[4], const uint32_t (&a)[4],
                                        uint32_t b0, uint32_t b1) {
    asm volatile(
        "mma.sync.aligned.m16n8k16.row.col.f32.f16.f16.f32 "
        "{%0,%1,%2,%3}, {%4,%5,%6,%7}, {%8,%9}, {%0,%1,%2,%3};"
        : "+f"(d[0]), "+f"(d[1]), "+f"(d[2]), "+f"(d[3])
        : "r"(a[0]), "r"(a[1]), "r"(a[2]), "r"(a[3]), "r"(b0), "r"(b1));
}

// ───────────── pre-kernel: tensor-core combine (64 blocks) | bc (8 blocks) ─────────────
// combine: 64x64 tile of Wc = Wv@Wo via HMMA.
//   A = Wv[k][j] (j contiguous) -> fp16 smem As[64 rows][32 j]
//   B = Wo[j][n] -> convert-TRANSPOSE -> fp16 smem Bs[64 n][32 j]
//   C[m=k][n] = sum_j A[m][j]*Bs[n][j]  (row.col mma)  -> store WcT to g_Bhi.
#define PROWB 80                      // smem row stride bytes (32 fp16 + pad)
#define PTILE (64 * PROWB)            // 5120 B per operand tile
#define PSTAGE (2 * PTILE)            // A+B one stage

__global__ __launch_bounds__(256)
void pre_kernel(const float* __restrict__ Wv, const float* __restrict__ Wo,
                const float* __restrict__ bv, const float* __restrict__ bo)
{
    const int b = blockIdx.x;
    const int tid = threadIdx.x;

    if (b < 64) {
        __shared__ char psm[2 * PSTAGE];   // 20480 B, double-buffered
        const uint32_t sbase = smem_u32(psm);
        const int lane = tid & 31;
        const int wid = tid >> 5;
        const int m0 = (b >> 3) * 64;      // k_out block
        const int n0 = (b & 7) * 64;       // n block
        const int wm = (wid >> 2) * 32;
        const int wn = (wid & 3) * 16;

        float4 aR[2], bR[2];

        auto lda = [&](int kb) {
            #pragma unroll
            for (int u = 0; u < 2; u++) {
                const int ch = tid + u * 256;
                const int r = ch >> 3, c = ch & 7;     // 64 rows x 8 f4
                aR[u] = __ldg(reinterpret_cast<const float4*>(
                    &Wv[(size_t)(m0 + r) * D + kb * 32 + c * 4]));
            }
        };
        auto ldb = [&](int kb) {
            #pragma unroll
            for (int u = 0; u < 2; u++) {
                const int ch = tid + u * 256;
                const int jr = ch >> 4, nc = ch & 15;  // 32 j-rows x 16 f4
                bR[u] = __ldg(reinterpret_cast<const float4*>(
                    &Wo[(size_t)(kb * 32 + jr) * D + n0 + nc * 4]));
            }
        };
        auto sts = [&](int s) {
            char* Ab = psm + s * PSTAGE;
            char* Bb = Ab + PTILE;
            #pragma unroll
            for (int u = 0; u < 2; u++) {
                const int ch = tid + u * 256;
                {   // A: straight convert
                    const int r = ch >> 3, c = ch & 7;
                    __half2 h0 = __floats2half2_rn(aR[u].x, aR[u].y);
                    __half2 h1 = __floats2half2_rn(aR[u].z, aR[u].w);
                    uint2 v;
                    v.x = *reinterpret_cast<uint32_t*>(&h0);
                    v.y = *reinterpret_cast<uint32_t*>(&h1);
                    *reinterpret_cast<uint2*>(Ab + r * PROWB + c * 8) = v;
                }
                {   // B: convert + transpose  Bs[n][j] = Wo[j][n]
                    const int jr = ch >> 4, nc = ch & 15;
                    const float f[4] = {bR[u].x, bR[u].y, bR[u].z, bR[u].w};
                    #pragma unroll
                    for (int i = 0; i < 4; i++)
                        *reinterpret_cast<__half*>(
                            Bb + (nc * 4 + i) * PROWB + jr * 2) =
                            __float2half_rn(f[i]);
                }
            }
        };

        float acc[2][2][4] = {};

        // prologue: chunk0 -> stage0; regs hold chunk1
        lda(0); ldb(0); sts(0);
        lda(1); ldb(1);

        #pragma unroll
        for (int kb = 0; kb < 16; kb++) {
            __syncthreads();
            // store chunk kb+1 into stage (kb^1)&1 (last read in iter kb-1)
            if (kb + 1 < 16) sts((kb + 1) & 1);
            if (kb + 2 < 16) { lda(kb + 2); ldb(kb + 2); }

            const uint32_t Ab = sbase + (uint32_t)(kb & 1) * PSTAGE;
            const uint32_t Bb = Ab + PTILE;
            #pragma unroll
            for (int ks = 0; ks < 2; ks++) {
                uint32_t a[2][4];
                #pragma unroll
                for (int mi = 0; mi < 2; mi++) {
                    uint32_t ra = Ab + (uint32_t)(wm + mi * 16 + (lane & 15)) * PROWB
                                + ks * 32 + ((lane >> 4) << 4);
                    ldsm_x4(a[mi], ra);
                }
                uint32_t bh[4];
                const int nl = wn + (lane & 7) + ((lane >> 4) << 3);
                uint32_t rb = Bb + (uint32_t)nl * PROWB
                            + ks * 32 + (((lane >> 3) & 1) << 4);
                ldsm_x4(bh, rb);
                #pragma unroll
                for (int mi = 0; mi < 2; mi++)
                    #pragma unroll
                    for (int ni = 0; ni < 2; ni++)
                        mma_f16(acc[mi][ni], a[mi], bh[ni * 2], bh[ni * 2 + 1]);
            }
            __syncthreads();
        }

        // epilogue: store WcT (transposed) fp16
        #pragma unroll
        for (int mi = 0; mi < 2; mi++) {
            const int row = m0 + wm + mi * 16 + (lane >> 2);   // k index
            #pragma unroll
            for (int ni = 0; ni < 2; ni++) {
                const int col = n0 + wn + ni * 8 + (lane & 3) * 2;   // n index
                g_Bhi[(size_t)col * D + row]           = __float2half_rn(acc[mi][ni][0]);
                g_Bhi[(size_t)(col + 1) * D + row]     = __float2half_rn(acc[mi][ni][1]);
                g_Bhi[(size_t)col * D + row + 8]       = __float2half_rn(acc[mi][ni][2]);
                g_Bhi[(size_t)(col + 1) * D + row + 8] = __float2half_rn(acc[mi][ni][3]);
            }
        }
        return;
    }

    // ---- bc role: 8 blocks x 64 n-cols, coalesced row reads ----
    {
        __shared__ float red[4][64];
        const int n0 = (b - 64) * 64;
        const int nn = tid & 63;
        const int kk = tid >> 6;
        float s = 0.f;
        #pragma unroll 16
        for (int k = kk; k < D; k += 4)
            s += bv[k] * Wo[(size_t)k * D + n0 + nn];
        red[kk][nn] = s;
        __syncthreads();
        if (tid < 64)
            g_bc[n0 + tid] = red[0][tid] + red[1][tid] + red[2][tid] + red[3][tid]
                           + bo[n0 + tid];
    }
}

// ───────────── main GEMM: fp32 A inline-converted, fp16 mma.sync ─────────────
// CTA 128x128, BK=32. A: 2-stage LDG->cvt->STS reg buffer. B: 4-stage cp.async,
// prefetch distance 3. Dependency-safe order: sta -> lda -> ldb -> MMA.
#define BM 128
#define BN 128
#define BKK 32
#define ROWB 80
#define A_TILE (128 * ROWB)
#define B_TILE (128 * ROWB)
#define A_STAGES 2
#define B_STAGES 4
#define B_BASE (A_STAGES * A_TILE)
#define SMEM_TOTAL (A_STAGES * A_TILE + B_STAGES * B_TILE)   // 61440 B
#define NKB (D / BKK)   // 16

__global__ __launch_bounds__(256, 2)
void mma_kernel(const float* __restrict__ x,
                const __half* __restrict__ Bhi,
                const float* __restrict__ bc, float* __restrict__ out)
{
    extern __shared__ char smem[];
    const uint32_t sb = smem_u32(smem);
    const int tid = threadIdx.x;
    const int lane = tid & 31;
    const int wid = tid >> 5;
    const int n0 = blockIdx.x * BN;   // n fast: 4 CTAs share an A tile
    const int m0 = blockIdx.y * BM;
    const int wm = (wid >> 2) * 64;
    const int wn = (wid & 3) * 32;

    const int ar = tid >> 3;          // 0..31
    const int ac = tid & 7;           // float4 column

    float4 areg[4];

    auto lda = [&](int kb) {
        const int k0 = kb * BKK;
        #pragma unroll
        for (int u = 0; u < 4; u++) {
            const int r = ar + u * 32;
            areg[u] = __ldg(reinterpret_cast<const float4*>(
                &x[(size_t)(m0 + r) * D + k0 + ac * 4]));
        }
    };
    auto sta = [&](int s) {
        char* base = smem + s * A_TILE;
        #pragma unroll
        for (int u = 0; u < 4; u++) {
            const int r = ar + u * 32;
            __half2 h0 = __floats2half2_rn(areg[u].x, areg[u].y);
            __half2 h1 = __floats2half2_rn(areg[u].z, areg[u].w);
            uint2 v;
            v.x = *reinterpret_cast<uint32_t*>(&h0);
            v.y = *reinterpret_cast<uint32_t*>(&h1);
            *reinterpret_cast<uint2*>(base + r * ROWB + ac * 8) = v;
        }
    };
    auto ldb = [&](int kb, int s) {
        const uint32_t base = sb + B_BASE + (uint32_t)s * B_TILE;
        const int k0 = kb * BKK;
        #pragma unroll
        for (int u = 0; u < 2; u++) {
            const int ch = tid + u * 256;
            const int r = ch >> 2, c = ch & 3;
            cp16(base + r * ROWB + c * 16,
                 Bhi + (size_t)(n0 + r) * D + k0 + c * 8);
        }
    };

    float acc[4][4][4] = {};

    // prologue: B stages 0..2 (distance 3), A stage 0, regs hold A(1)
    ldb(0, 0); cp_commit();
    ldb(1, 1); cp_commit();
    ldb(2, 2); cp_commit();
    lda(0); sta(0);
    lda(1);

    #pragma unroll
    for (int kb = 0; kb < NKB; kb++) {
        if (kb <= NKB - 3)      cp_wait<2>();
        else if (kb == NKB - 2) cp_wait<1>();
        else                    cp_wait<0>();
        __syncthreads();

        // dependency-safe front-loading
        if (kb + 1 < NKB) sta((kb + 1) & 1);
        if (kb + 2 < NKB) lda(kb + 2);
        if (kb + 3 < NKB) ldb(kb + 3, (kb + 3) & 3);
        cp_commit();

        const uint32_t baseA = sb + (uint32_t)(kb & 1) * A_TILE;
        const uint32_t baseB = sb + B_BASE + (uint32_t)(kb & 3) * B_TILE;
        #pragma unroll
        for (int ks = 0; ks < 2; ks++) {
            uint32_t a[4][4];
            #pragma unroll
            for (int mi = 0; mi < 4; mi++) {
                uint32_t ra = baseA + (uint32_t)(wm + mi * 16 + (lane & 15)) * ROWB
                            + ks * 32 + ((lane >> 4) << 4);
                ldsm_x4(a[mi], ra);
            }
            uint32_t bh[2][4];
            #pragma unroll
            for (int bi = 0; bi < 2; bi++) {
                const int nl = wn + bi * 16 + (lane & 7) + ((lane >> 4) << 3);
                uint32_t rb = baseB + (uint32_t)nl * ROWB
                            + ks * 32 + (((lane >> 3) & 1) << 4);
                ldsm_x4(bh[bi], rb);
            }
            #pragma unroll
            for (int mi = 0; mi < 4; mi++)
                #pragma unroll
                for (int ni = 0; ni < 4; ni++) {
                    const int bi = ni >> 1, p = (ni & 1) * 2;
                    mma_f16(acc[mi][ni], a[mi], bh[bi][p], bh[bi][p + 1]);
                }
        }
    }

    // epilogue: fp32 stores + bias
    #pragma unroll
    for (int mi = 0; mi < 4; mi++) {
        const int r = m0 + wm + mi * 16 + (lane >> 2);
        #pragma unroll
        for (int ni = 0; ni < 4; ni++) {
            const int c = n0 + wn + ni * 8 + (lane & 3) * 2;
            float2 bv = *reinterpret_cast<const float2*>(&bc[c]);
            float2 v0 = make_float2(acc[mi][ni][0] + bv.x, acc[mi][ni][1] + bv.y);
            float2 v1 = make_float2(acc[mi][ni][2] + bv.x, acc[mi][ni][3] + bv.y);
            *reinterpret_cast<float2*>(&out[(size_t)r * D + c]) = v0;
            *reinterpret_cast<float2*>(&out[(size_t)(r + 8) * D + c]) = v1;
        }
    }
}

// ───────────────────────── host ─────────────────────────
extern "C" void kernel_launch(void* const* d_in, const int* in_sizes, int n_in,
                              void* d_out, int out_size)
{
    // order: x, H, W, Wq, bq, Wk, bk, Wv, bv, Wo, bo, Woff1, boff1, Woff2, boff2
    const float* x  = (const float*)d_in[0];
    const float* Wv = (const float*)d_in[7];
    const float* bv = (const float*)d_in[8];
    const float* Wo = (const float*)d_in[9];
    const float* bo = (const float*)d_in[10];
    float* out = (float*)d_out;

    const int M = in_sizes[0] / D;   // 16384 tokens

    __half* bhi;
    float* bc;
    cudaGetSymbolAddress((void**)&bhi, g_Bhi);
    cudaGetSymbolAddress((void**)&bc,  g_bc);

    static bool attr_set = false;
    if (!attr_set) {
        cudaFuncSetAttribute(mma_kernel,
                             cudaFuncAttributeMaxDynamicSharedMemorySize, SMEM_TOTAL);
        attr_set = true;
    }

    pre_kernel<<<64 + 8, 256>>>(Wv, Wo, bv, bo);
    mma_kernel<<<dim3(D / BN, M / BM), 256, SMEM_TOTAL>>>(x, bhi, bc, out);
}

// round 12
// speedup vs baseline: 1.2722x; 1.0429x over previous
#include <cuda_runtime.h>
#include <cuda_fp16.h>
#include <cstdint>

// out = x @ (Wv@Wo) + (bv@Wo + bo)   (algebraic collapse, validated r1)
// pre_kernel: tensor-core combine (bids 0-63) | bc (64-71) | x->fp16 convert (72+)
// mma_kernel: pure cp.async fp16 HMMA GEMM (no fp32 path, no inline convert).

#define D 512
#define MTOK 16384

__device__ __half g_Ahi[MTOK * D]; // x fp16
__device__ __half g_Bhi[D * D];    // WcT fp16  [n][k]
__device__ float g_bc[D];

// ───────────────────────── helpers ─────────────────────────
__device__ __forceinline__ uint32_t smem_u32(const void* p) {
    uint32_t a;
    asm("{ .reg .u64 t; cvta.to.shared.u64 t, %1; cvt.u32.u64 %0, t; }"
        : "=r"(a) : "l"(p));
    return a;
}
__device__ __forceinline__ void cp16(uint32_t dst, const void* src) {
    asm volatile("cp.async.cg.shared.global [%0], [%1], 16;"
                 :: "r"(dst), "l"(src) : "memory");
}
__device__ __forceinline__ void cp_commit() {
    asm volatile("cp.async.commit_group;" ::: "memory");
}
template <int N>
__device__ __forceinline__ void cp_wait() {
    asm volatile("cp.async.wait_group %0;" :: "n"(N) : "memory");
}
__device__ __forceinline__ void ldsm_x4(uint32_t (&r)[4], uint32_t addr) {
    asm volatile("ldmatrix.sync.aligned.m8n8.x4.shared.b16 {%0,%1,%2,%3}, [%4];"
                 : "=r"(r[0]), "=r"(r[1]), "=r"(r[2]), "=r"(r[3]) : "r"(addr));
}
__device__ __forceinline__ void mma_f16(float (&d)[4], const uint32_t (&a)[4],
                                        uint32_t b0, uint32_t b1) {
    asm volatile(
        "mma.sync.aligned.m16n8k16.row.col.f32.f16.f16.f32 "
        "{%0,%1,%2,%3}, {%4,%5,%6,%7}, {%8,%9}, {%0,%1,%2,%3};"
        : "+f"(d[0]), "+f"(d[1]), "+f"(d[2]), "+f"(d[3])
        : "r"(a[0]), "r"(a[1]), "r"(a[2]), "r"(a[3]), "r"(b0), "r"(b1));
}

// ───────────── pre-kernel ─────────────
#define PROWB 80
#define PTILE (64 * PROWB)
#define PSTAGE (2 * PTILE)
#define N_COMBINE 64
#define N_BC 8
#define N_PRE (N_COMBINE + N_BC)      // 72
#define N_CONV (MTOK * D / 2048)      // 4096 convert blocks (8 elems/thread)

__global__ __launch_bounds__(256)
void pre_kernel(const float* __restrict__ x,
                const float* __restrict__ Wv, const float* __restrict__ Wo,
                const float* __restrict__ bv, const float* __restrict__ bo)
{
    const int b = blockIdx.x;
    const int tid = threadIdx.x;

    if (b >= N_PRE) {
        // ---- convert role: x -> fp16 (highest bids; scheduled after combine) ----
        size_t i = ((size_t)(b - N_PRE) * 256 + tid) * 8;
        float4 v0 = *reinterpret_cast<const float4*>(x + i);
        float4 v1 = *reinterpret_cast<const float4*>(x + i + 4);
        __half2 h[4];
        h[0] = __floats2half2_rn(v0.x, v0.y);
        h[1] = __floats2half2_rn(v0.z, v0.w);
        h[2] = __floats2half2_rn(v1.x, v1.y);
        h[3] = __floats2half2_rn(v1.z, v1.w);
        *reinterpret_cast<uint4*>(&g_Ahi[i]) = *reinterpret_cast<uint4*>(h);
        return;
    }

    if (b < N_COMBINE) {
        // ---- combine: 64x64 tile of Wc = Wv@Wo via HMMA ----
        __shared__ char psm[2 * PSTAGE];
        const uint32_t sbase = smem_u32(psm);
        const int lane = tid & 31;
        const int wid = tid >> 5;
        const int m0 = (b >> 3) * 64;
        const int n0 = (b & 7) * 64;
        const int wm = (wid >> 2) * 32;
        const int wn = (wid & 3) * 16;

        float4 aR[2], bR[2];

        auto lda = [&](int kb) {
            #pragma unroll
            for (int u = 0; u < 2; u++) {
                const int ch = tid + u * 256;
                const int r = ch >> 3, c = ch & 7;
                aR[u] = __ldg(reinterpret_cast<const float4*>(
                    &Wv[(size_t)(m0 + r) * D + kb * 32 + c * 4]));
            }
        };
        auto ldb = [&](int kb) {
            #pragma unroll
            for (int u = 0; u < 2; u++) {
                const int ch = tid + u * 256;
                const int jr = ch >> 4, nc = ch & 15;
                bR[u] = __ldg(reinterpret_cast<const float4*>(
                    &Wo[(size_t)(kb * 32 + jr) * D + n0 + nc * 4]));
            }
        };
        auto sts = [&](int s) {
            char* Ab = psm + s * PSTAGE;
            char* Bb = Ab + PTILE;
            #pragma unroll
            for (int u = 0; u < 2; u++) {
                const int ch = tid + u * 256;
                {
                    const int r = ch >> 3, c = ch & 7;
                    __half2 h0 = __floats2half2_rn(aR[u].x, aR[u].y);
                    __half2 h1 = __floats2half2_rn(aR[u].z, aR[u].w);
                    uint2 v;
                    v.x = *reinterpret_cast<uint32_t*>(&h0);
                    v.y = *reinterpret_cast<uint32_t*>(&h1);
                    *reinterpret_cast<uint2*>(Ab + r * PROWB + c * 8) = v;
                }
                {
                    const int jr = ch >> 4, nc = ch & 15;
                    const float f[4] = {bR[u].x, bR[u].y, bR[u].z, bR[u].w};
                    #pragma unroll
                    for (int i = 0; i < 4; i++)
                        *reinterpret_cast<__half*>(
                            Bb + (nc * 4 + i) * PROWB + jr * 2) =
                            __float2half_rn(f[i]);
                }
            }
        };

        float acc[2][2][4] = {};
        lda(0); ldb(0); sts(0);
        lda(1); ldb(1);

        #pragma unroll
        for (int kb = 0; kb < 16; kb++) {
            __syncthreads();
            if (kb + 1 < 16) sts((kb + 1) & 1);
            if (kb + 2 < 16) { lda(kb + 2); ldb(kb + 2); }

            const uint32_t Ab = sbase + (uint32_t)(kb & 1) * PSTAGE;
            const uint32_t Bb = Ab + PTILE;
            #pragma unroll
            for (int ks = 0; ks < 2; ks++) {
                uint32_t a[2][4];
                #pragma unroll
                for (int mi = 0; mi < 2; mi++) {
                    uint32_t ra = Ab + (uint32_t)(wm + mi * 16 + (lane & 15)) * PROWB
                                + ks * 32 + ((lane >> 4) << 4);
                    ldsm_x4(a[mi], ra);
                }
                uint32_t bh[4];
                const int nl = wn + (lane & 7) + ((lane >> 4) << 3);
                uint32_t rb = Bb + (uint32_t)nl * PROWB
                            + ks * 32 + (((lane >> 3) & 1) << 4);
                ldsm_x4(bh, rb);
                #pragma unroll
                for (int mi = 0; mi < 2; mi++)
                    #pragma unroll
                    for (int ni = 0; ni < 2; ni++)
                        mma_f16(acc[mi][ni], a[mi], bh[ni * 2], bh[ni * 2 + 1]);
            }
            __syncthreads();
        }

        #pragma unroll
        for (int mi = 0; mi < 2; mi++) {
            const int row = m0 + wm + mi * 16 + (lane >> 2);
            #pragma unroll
            for (int ni = 0; ni < 2; ni++) {
                const int col = n0 + wn + ni * 8 + (lane & 3) * 2;
                g_Bhi[(size_t)col * D + row]           = __float2half_rn(acc[mi][ni][0]);
                g_Bhi[(size_t)(col + 1) * D + row]     = __float2half_rn(acc[mi][ni][1]);
                g_Bhi[(size_t)col * D + row + 8]       = __float2half_rn(acc[mi][ni][2]);
                g_Bhi[(size_t)(col + 1) * D + row + 8] = __float2half_rn(acc[mi][ni][3]);
            }
        }
        return;
    }

    // ---- bc role ----
    {
        __shared__ float red[4][64];
        const int n0 = (b - N_COMBINE) * 64;
        const int nn = tid & 63;
        const int kk = tid >> 6;
        float s = 0.f;
        #pragma unroll 16
        for (int k = kk; k < D; k += 4)
            s += bv[k] * Wo[(size_t)k * D + n0 + nn];
        red[kk][nn] = s;
        __syncthreads();
        if (tid < 64)
            g_bc[n0 + tid] = red[0][tid] + red[1][tid] + red[2][tid] + red[3][tid]
                           + bo[n0 + tid];
    }
}

// ───────────── main GEMM: all-cp.async fp16 HMMA ─────────────
// CTA 128x128, BK=32, 4 stages (A+B per stage), one barrier per iter.
#define BM 128
#define BN 128
#define BKK 32
#define ROWB 80
#define OP_TILE (128 * ROWB)          // 10240 B per operand
#define STAGE_B (2 * OP_TILE)         // 20480 B (A + B)
#define NSTAGE 4
#define SMEM_TOTAL (NSTAGE * STAGE_B) // 81920 B
#define NKB (D / BKK)                 // 16

__global__ __launch_bounds__(256, 2)
void mma_kernel(const __half* __restrict__ Ahi,
                const __half* __restrict__ Bhi,
                const float* __restrict__ bc, float* __restrict__ out)
{
    extern __shared__ char smem[];
    const uint32_t sb = smem_u32(smem);
    const int tid = threadIdx.x;
    const int lane = tid & 31;
    const int wid = tid >> 5;
    const int n0 = blockIdx.x * BN;   // n fast: 4 CTAs share an A tile
    const int m0 = blockIdx.y * BM;
    const int wm = (wid >> 2) * 64;
    const int wn = (wid & 3) * 32;

    auto ldab = [&](int kb, int s) {
        const uint32_t base = sb + (uint32_t)s * STAGE_B;
        const int k0 = kb * BKK;
        #pragma unroll
        for (int u = 0; u < 2; u++) {
            const int ch = tid + u * 256;
            const int r = ch >> 2, c = ch & 3;   // 128 rows x 4 16B-chunks
            cp16(base + r * ROWB + c * 16,
                 Ahi + (size_t)(m0 + r) * D + k0 + c * 8);
            cp16(base + OP_TILE + r * ROWB + c * 16,
                 Bhi + (size_t)(n0 + r) * D + k0 + c * 8);
        }
    };

    float acc[4][4][4] = {};

    // prologue: stages 0..2 (prefetch distance 3)
    ldab(0, 0); cp_commit();
    ldab(1, 1); cp_commit();
    ldab(2, 2); cp_commit();

    #pragma unroll
    for (int kb = 0; kb < NKB; kb++) {
        cp_wait<2>();          // stage kb complete (uniform: commits keep coming)
        __syncthreads();

        // prefetch kb+3 into stage (kb+3)&3 = (kb-1)&3, read pre-barrier
        if (kb + 3 < NKB) ldab(kb + 3, (kb + 3) & 3);
        cp_commit();

        const uint32_t baseA = sb + (uint32_t)(kb & 3) * STAGE_B;
        const uint32_t baseB = baseA + OP_TILE;
        #pragma unroll
        for (int ks = 0; ks < 2; ks++) {
            uint32_t a[4][4];
            #pragma unroll
            for (int mi = 0; mi < 4; mi++) {
                uint32_t ra = baseA + (uint32_t)(wm + mi * 16 + (lane & 15)) * ROWB
                            + ks * 32 + ((lane >> 4) << 4);
                ldsm_x4(a[mi], ra);
            }
            uint32_t bh[2][4];
            #pragma unroll
            for (int bi = 0; bi < 2; bi++) {
                const int nl = wn + bi * 16 + (lane & 7) + ((lane >> 4) << 3);
                uint32_t rb = baseB + (uint32_t)nl * ROWB
                            + ks * 32 + (((lane >> 3) & 1) << 4);
                ldsm_x4(bh[bi], rb);
            }
            #pragma unroll
            for (int mi = 0; mi < 4; mi++)
                #pragma unroll
                for (int ni = 0; ni < 4; ni++) {
                    const int bi = ni >> 1, p = (ni & 1) * 2;
                    mma_f16(acc[mi][ni], a[mi], bh[bi][p], bh[bi][p + 1]);
                }
        }
    }

    // epilogue: fp32 stores + bias
    #pragma unroll
    for (int mi = 0; mi < 4; mi++) {
        const int r = m0 + wm + mi * 16 + (lane >> 2);
        #pragma unroll
        for (int ni = 0; ni < 4; ni++) {
            const int c = n0 + wn + ni * 8 + (lane & 3) * 2;
            float2 bv = *reinterpret_cast<const float2*>(&bc[c]);
            float2 v0 = make_float2(acc[mi][ni][0] + bv.x, acc[mi][ni][1] + bv.y);
            float2 v1 = make_float2(acc[mi][ni][2] + bv.x, acc[mi][ni][3] + bv.y);
            *reinterpret_cast<float2*>(&out[(size_t)r * D + c]) = v0;
            *reinterpret_cast<float2*>(&out[(size_t)(r + 8) * D + c]) = v1;
        }
    }
}

// ───────────────────────── host ─────────────────────────
extern "C" void kernel_launch(void* const* d_in, const int* in_sizes, int n_in,
                              void* d_out, int out_size)
{
    // order: x, H, W, Wq, bq, Wk, bk, Wv, bv, Wo, bo, Woff1, boff1, Woff2, boff2
    const float* x  = (const float*)d_in[0];
    const float* Wv = (const float*)d_in[7];
    const float* bv = (const float*)d_in[8];
    const float* Wo = (const float*)d_in[9];
    const float* bo = (const float*)d_in[10];
    float* out = (float*)d_out;

    const int M = in_sizes[0] / D;   // 16384 tokens

    __half *ahi, *bhi;
    float* bc;
    cudaGetSymbolAddress((void**)&ahi, g_Ahi);
    cudaGetSymbolAddress((void**)&bhi, g_Bhi);
    cudaGetSymbolAddress((void**)&bc,  g_bc);

    static bool attr_set = false;
    if (!attr_set) {
        cudaFuncSetAttribute(mma_kernel,
                             cudaFuncAttributeMaxDynamicSharedMemorySize, SMEM_TOTAL);
        attr_set = true;
    }

    pre_kernel<<<N_PRE + N_CONV, 256>>>(x, Wv, Wo, bv, bo);
    mma_kernel<<<dim3(D / BN, M / BM), 256, SMEM_TOTAL>>>(ahi, bhi, bc, out);
}